// round 2
// baseline (speedup 1.0000x reference)
#include <cuda_runtime.h>
#include <cstdint>

#define BATCHN 8
#define TT 2048
#define EE 1024
#define DD 128
#define MTOT (BATCHN*TT)

// Scratch for Q,K,V projections (8 MB each) — __device__ globals per allocation rules.
__device__ float g_q[MTOT*DD];
__device__ float g_k[MTOT*DD];
__device__ float g_v[MTOT*DD];

// ---------------------------------------------------------------------------
// QKV projection via TF32 mma.sync (m16n8k8).
// C[16384,128] = X[16384,1024] @ W[1024,128].  CTA tile 128x128, KT=32.
// 8 warps (4 M x 2 N), warp tile 32x64.  Smem [k][*] stride 136 -> all
// fragment LDS bank-conflict-free.  grid = (128, 3): y selects Wq/Wk/Wv.
// ---------------------------------------------------------------------------
#define SA 136
#define KT 32

__device__ __forceinline__ float to_tf32(float x) {
  float y;
  asm("cvt.rna.tf32.f32 %0, %1;" : "=f"(y) : "f"(x));
  return y;
}

__device__ __forceinline__ void mma_tf32(float* c, const float* a, const float* b) {
  asm volatile(
      "mma.sync.aligned.m16n8k8.row.col.f32.tf32.tf32.f32 "
      "{%0,%1,%2,%3}, {%4,%5,%6,%7}, {%8,%9}, {%0,%1,%2,%3};"
      : "+f"(c[0]), "+f"(c[1]), "+f"(c[2]), "+f"(c[3])
      : "r"(__float_as_uint(a[0])), "r"(__float_as_uint(a[1])),
        "r"(__float_as_uint(a[2])), "r"(__float_as_uint(a[3])),
        "r"(__float_as_uint(b[0])), "r"(__float_as_uint(b[1])));
}

__global__ __launch_bounds__(256) void qkv_mma_kernel(
    const float* __restrict__ X, const float* __restrict__ Wq,
    const float* __restrict__ Wk, const float* __restrict__ Wv) {
  __shared__ float As[KT * SA];  // [k][m]
  __shared__ float Bs[KT * SA];  // [k][n]

  const int which = blockIdx.y;
  const float* __restrict__ W = (which == 0) ? Wq : (which == 1) ? Wk : Wv;
  float* __restrict__ outp = (which == 0) ? g_q : (which == 1) ? g_k : g_v;

  const int m0 = blockIdx.x * 128;
  const int tid = threadIdx.x;
  const int warp = tid >> 5;
  const int lane = tid & 31;
  const int warp_m = (warp >> 1) * 32;   // 0,32,64,96
  const int warp_n = (warp & 1) * 64;    // 0,64
  const int fr = lane >> 2;              // fragment row 0..7
  const int fc = lane & 3;               // fragment col 0..3

  // loader indices
  const int lm = tid & 127;              // X row within tile
  const int lks = (tid >> 7) * 16;       // X k start (0 or 16)
  const int bn4 = (lane) * 4;            // W col (float4)
  const int bkr = warp;                  // W k row base 0..7

  float acc[2][8][4];
#pragma unroll
  for (int mt = 0; mt < 2; mt++)
#pragma unroll
    for (int nt = 0; nt < 8; nt++)
#pragma unroll
      for (int i = 0; i < 4; i++) acc[mt][nt][i] = 0.f;

  // prefetch tile 0
  float4 xv[4], wv[4];
#pragma unroll
  for (int i = 0; i < 4; i++) {
    xv[i] = *(const float4*)&X[(size_t)(m0 + lm) * EE + lks + i * 4];
    wv[i] = *(const float4*)&W[(size_t)(bkr + 8 * i) * DD + bn4];
  }

  for (int kt = 0; kt < EE / KT; kt++) {
    __syncthreads();  // previous tile compute complete
    // stage with tf32 rounding
#pragma unroll
    for (int i = 0; i < 4; i++) {
      const float* p = (const float*)&xv[i];
#pragma unroll
      for (int j = 0; j < 4; j++) As[(lks + i * 4 + j) * SA + lm] = to_tf32(p[j]);
      float4 w4 = wv[i];
      w4.x = to_tf32(w4.x); w4.y = to_tf32(w4.y);
      w4.z = to_tf32(w4.z); w4.w = to_tf32(w4.w);
      *(float4*)&Bs[(bkr + 8 * i) * SA + bn4] = w4;
    }
    __syncthreads();

    if (kt + 1 < EE / KT) {
      const int k0 = (kt + 1) * KT;
#pragma unroll
      for (int i = 0; i < 4; i++) {
        xv[i] = *(const float4*)&X[(size_t)(m0 + lm) * EE + k0 + lks + i * 4];
        wv[i] = *(const float4*)&W[(size_t)(k0 + bkr + 8 * i) * DD + bn4];
      }
    }

#pragma unroll
    for (int ks = 0; ks < 4; ks++) {
      const int k = ks * 8;
      float a[2][4];
#pragma unroll
      for (int mt = 0; mt < 2; mt++) {
        const int m = warp_m + mt * 16 + fr;
        a[mt][0] = As[(k + fc) * SA + m];
        a[mt][1] = As[(k + fc) * SA + m + 8];
        a[mt][2] = As[(k + fc + 4) * SA + m];
        a[mt][3] = As[(k + fc + 4) * SA + m + 8];
      }
      float b[8][2];
#pragma unroll
      for (int nt = 0; nt < 8; nt++) {
        const int n = warp_n + nt * 8 + fr;
        b[nt][0] = Bs[(k + fc) * SA + n];
        b[nt][1] = Bs[(k + fc + 4) * SA + n];
      }
#pragma unroll
      for (int mt = 0; mt < 2; mt++)
#pragma unroll
        for (int nt = 0; nt < 8; nt++) mma_tf32(acc[mt][nt], a[mt], b[nt]);
    }
  }

  // writeback: c0,c1 -> (row, 2c),(row,2c+1); c2,c3 -> row+8
#pragma unroll
  for (int mt = 0; mt < 2; mt++) {
    const size_t row = (size_t)(m0 + warp_m + mt * 16 + fr);
#pragma unroll
    for (int nt = 0; nt < 8; nt++) {
      const int col = warp_n + nt * 8 + fc * 2;
      float2 lo = make_float2(acc[mt][nt][0], acc[mt][nt][1]);
      float2 hi = make_float2(acc[mt][nt][2], acc[mt][nt][3]);
      *(float2*)&outp[row * DD + col] = lo;
      *(float2*)&outp[(row + 8) * DD + col] = hi;
    }
  }
}

// ---------------------------------------------------------------------------
// Causal flash attention (fp32, online softmax) — unchanged from R0.
// ---------------------------------------------------------------------------
#define BQ 64
#define BK 32
#define SQ 132
#define SKS 132
#define SV 128
#define SSS 33

#define OFF_Q 0
#define OFF_K (OFF_Q + BQ * SQ)
#define OFF_V (OFF_K + BK * SKS)
#define OFF_S (OFF_V + BK * SV)
#define OFF_M (OFF_S + BQ * SSS)
#define OFF_L (OFF_M + BQ)
#define OFF_A (OFF_L + BQ)
#define SMEM_FLOATS (OFF_A + BQ)

__global__ __launch_bounds__(256) void attn_kernel(float* __restrict__ out) {
  extern __shared__ float sm_[];
  float* Qs = sm_ + OFF_Q;
  float* Ks = sm_ + OFF_K;
  float* Vs = sm_ + OFF_V;
  float* Ss = sm_ + OFF_S;
  float* mrow = sm_ + OFF_M;
  float* lrow = sm_ + OFF_L;
  float* arow = sm_ + OFF_A;

  const int b = blockIdx.y;
  const int tid = threadIdx.x;
  const float* __restrict__ qp = g_q + (size_t)b * TT * DD;
  const float* __restrict__ kp = g_k + (size_t)b * TT * DD;
  const float* __restrict__ vp = g_v + (size_t)b * TT * DD;
  const float scale = 0.08838834764831845f;

  const int rm = tid >> 5, rn = tid & 31;
  const int smi = tid >> 3, snj = tid & 7;

  for (int pass = 0; pass < 2; pass++) {
    const int qblk = pass ? (TT / BQ - 1 - (int)blockIdx.x) : (int)blockIdx.x;
    __syncthreads();

#pragma unroll
    for (int it = 0; it < 8; it++) {
      int idx = tid + it * 256;
      int r = idx >> 5;
      int d4 = (idx & 31) << 2;
      float4 v = *(const float4*)&qp[(size_t)(qblk * BQ + r) * DD + d4];
      Qs[r * SQ + d4 + 0] = v.x * scale;
      Qs[r * SQ + d4 + 1] = v.y * scale;
      Qs[r * SQ + d4 + 2] = v.z * scale;
      Qs[r * SQ + d4 + 3] = v.w * scale;
    }
    if (tid < BQ) {
      mrow[tid] = -1e30f;
      lrow[tid] = 0.f;
    }

    float o[8][4];
#pragma unroll
    for (int i = 0; i < 8; i++)
#pragma unroll
      for (int j = 0; j < 4; j++) o[i][j] = 0.f;

    const int nkt = 2 * (qblk + 1);
    for (int kt = 0; kt < nkt; kt++) {
#pragma unroll
      for (int it = 0; it < 4; it++) {
        int idx = tid + it * 256;
        int r = idx >> 5;
        int d4 = (idx & 31) << 2;
        float4 kv = *(const float4*)&kp[(size_t)(kt * BK + r) * DD + d4];
        Ks[r * SKS + d4 + 0] = kv.x;
        Ks[r * SKS + d4 + 1] = kv.y;
        Ks[r * SKS + d4 + 2] = kv.z;
        Ks[r * SKS + d4 + 3] = kv.w;
        float4 vv = *(const float4*)&vp[(size_t)(kt * BK + r) * DD + d4];
        *(float4*)&Vs[r * SV + d4] = vv;
      }
      __syncthreads();

      float s[2][4];
#pragma unroll
      for (int i = 0; i < 2; i++)
#pragma unroll
        for (int j = 0; j < 4; j++) s[i][j] = 0.f;

#pragma unroll 8
      for (int d = 0; d < DD; d += 4) {
        float4 q0 = *(const float4*)&Qs[smi * SQ + d];
        float4 q1 = *(const float4*)&Qs[(smi + 32) * SQ + d];
        float4 k0 = *(const float4*)&Ks[snj * SKS + d];
        float4 k1 = *(const float4*)&Ks[(snj + 8) * SKS + d];
        float4 k2 = *(const float4*)&Ks[(snj + 16) * SKS + d];
        float4 k3 = *(const float4*)&Ks[(snj + 24) * SKS + d];
        s[0][0] += q0.x * k0.x + q0.y * k0.y + q0.z * k0.z + q0.w * k0.w;
        s[0][1] += q0.x * k1.x + q0.y * k1.y + q0.z * k1.z + q0.w * k1.w;
        s[0][2] += q0.x * k2.x + q0.y * k2.y + q0.z * k2.z + q0.w * k2.w;
        s[0][3] += q0.x * k3.x + q0.y * k3.y + q0.z * k3.z + q0.w * k3.w;
        s[1][0] += q1.x * k0.x + q1.y * k0.y + q1.z * k0.z + q1.w * k0.w;
        s[1][1] += q1.x * k1.x + q1.y * k1.y + q1.z * k1.z + q1.w * k1.w;
        s[1][2] += q1.x * k2.x + q1.y * k2.y + q1.z * k2.z + q1.w * k2.w;
        s[1][3] += q1.x * k3.x + q1.y * k3.y + q1.z * k3.z + q1.w * k3.w;
      }

      if (kt >= 2 * qblk) {
#pragma unroll
        for (int i = 0; i < 2; i++)
#pragma unroll
          for (int j = 0; j < 4; j++) {
            int qg = qblk * BQ + smi + 32 * i;
            int kg = kt * BK + snj + 8 * j;
            if (kg > qg) s[i][j] = -1e30f;
          }
      }
#pragma unroll
      for (int i = 0; i < 2; i++)
#pragma unroll
        for (int j = 0; j < 4; j++)
          Ss[(smi + 32 * i) * SSS + snj + 8 * j] = s[i][j];
      __syncthreads();

      if (tid < BQ) {
        float mo = mrow[tid];
        float mn = mo;
#pragma unroll
        for (int c = 0; c < BK; c++) mn = fmaxf(mn, Ss[tid * SSS + c]);
        float al = __expf(mo - mn);
        float sum = 0.f;
#pragma unroll
        for (int c = 0; c < BK; c++) {
          float p = __expf(Ss[tid * SSS + c] - mn);
          Ss[tid * SSS + c] = p;
          sum += p;
        }
        lrow[tid] = lrow[tid] * al + sum;
        mrow[tid] = mn;
        arow[tid] = al;
      }
      __syncthreads();

      float al[8];
#pragma unroll
      for (int i = 0; i < 8; i++) al[i] = arow[rm + 8 * i];
#pragma unroll
      for (int i = 0; i < 8; i++)
#pragma unroll
        for (int j = 0; j < 4; j++) o[i][j] *= al[i];

#pragma unroll 4
      for (int k = 0; k < BK; k++) {
        float4 v = *(const float4*)&Vs[k * SV + rn * 4];
#pragma unroll
        for (int i = 0; i < 8; i++) {
          float p = Ss[(rm + 8 * i) * SSS + k];
          o[i][0] += p * v.x;
          o[i][1] += p * v.y;
          o[i][2] += p * v.z;
          o[i][3] += p * v.w;
        }
      }
      __syncthreads();
    }

#pragma unroll
    for (int i = 0; i < 8; i++) {
      int r = rm + 8 * i;
      float inv = 1.f / lrow[r];
      size_t base = ((size_t)b * TT + (size_t)qblk * BQ + r) * DD;
      float4 ov = make_float4(o[i][0] * inv, o[i][1] * inv, o[i][2] * inv,
                              o[i][3] * inv);
      *(float4*)&out[base + rn * 4] = ov;
    }
  }
}

// ---------------------------------------------------------------------------
extern "C" void kernel_launch(void* const* d_in, const int* in_sizes, int n_in,
                              void* d_out, int out_size) {
  const float* X = (const float*)d_in[0];
  const float* Wq = (const float*)d_in[1];
  const float* Wk = (const float*)d_in[2];
  const float* Wv = (const float*)d_in[3];
  float* out = (float*)d_out;

  qkv_mma_kernel<<<dim3(128, 3), 256>>>(X, Wq, Wk, Wv);

  const int smem_bytes = SMEM_FLOATS * (int)sizeof(float);
  cudaFuncSetAttribute((const void*)attn_kernel,
                       cudaFuncAttributeMaxDynamicSharedMemorySize, smem_bytes);
  attn_kernel<<<dim3(16, BATCHN), 256, smem_bytes>>>(out);
}

// round 4
// speedup vs baseline: 1.1537x; 1.1537x over previous
#include <cuda_runtime.h>
#include <cstdint>

#define BATCHN 8
#define TT 2048
#define EE 1024
#define DD 128
#define MTOT (BATCHN*TT)

// Scratch for Q,K,V projections (8 MB each) — __device__ globals per allocation rules.
__device__ float g_q[MTOT*DD];
__device__ float g_k[MTOT*DD];
__device__ float g_v[MTOT*DD];

typedef unsigned long long ull;

// ---- packed f32x2 helpers (Blackwell baseline-family ops, no 'a' target) ----
__device__ __forceinline__ ull packf2(float x, float y) {
  ull r;
  asm("mov.b64 %0, {%1, %2};" : "=l"(r) : "f"(x), "f"(y));
  return r;
}
__device__ __forceinline__ void fma2(ull& c, ull a, ull b) {
  asm("fma.rn.f32x2 %0, %1, %2, %0;" : "+l"(c) : "l"(a), "l"(b));
}
__device__ __forceinline__ ull mul2(ull a, ull b) {
  ull r;
  asm("mul.rn.f32x2 %0, %1, %2;" : "=l"(r) : "l"(a), "l"(b));
  return r;
}
union F2U { ull u; float2 f; };

// ---------------------------------------------------------------------------
// QKV projection: out = X @ W, fp32 with packed FFMA2.
// Tile 128x128, BK=8, 256 threads, 8(m) x 4(n-pair) per-thread micro-tile.
// gridDim = (128, 3): y selects Wq/Wk/Wv.
// ---------------------------------------------------------------------------
__global__ __launch_bounds__(256) void qkv_gemm_kernel(
    const float* __restrict__ X, const float* __restrict__ Wq,
    const float* __restrict__ Wk, const float* __restrict__ Wv) {
  __shared__ float Xs[8][128];   // [k][m]
  __shared__ float Ws[8][128];   // [k][n]
  const int which = blockIdx.y;
  const float* __restrict__ W = (which == 0) ? Wq : (which == 1) ? Wk : Wv;
  float* __restrict__ outp = (which == 0) ? g_q : (which == 1) ? g_k : g_v;

  const int m0 = blockIdx.x * 128;
  const int tid = threadIdx.x;
  const int tm = tid >> 4;
  const int tn = tid & 15;
  const int xm = tid >> 1;
  const int xk = (tid & 1) << 2;
  const int wk = tid >> 5;
  const int wn = (tid & 31) << 2;

  ull acc2[8][4];
#pragma unroll
  for (int i = 0; i < 8; i++)
#pragma unroll
    for (int j = 0; j < 4; j++) acc2[i][j] = 0ull;

  for (int k0 = 0; k0 < EE; k0 += 8) {
    float4 xv = *(const float4*)&X[(size_t)(m0 + xm) * EE + k0 + xk];
    float4 wv = *(const float4*)&W[(size_t)(k0 + wk) * DD + wn];
    __syncthreads();
    Xs[xk + 0][xm] = xv.x;
    Xs[xk + 1][xm] = xv.y;
    Xs[xk + 2][xm] = xv.z;
    Xs[xk + 3][xm] = xv.w;
    *(float4*)&Ws[wk][wn] = wv;
    __syncthreads();
#pragma unroll
    for (int kk = 0; kk < 8; kk++) {
      float a[8];
      *(float4*)&a[0] = *(const float4*)&Xs[kk][tm * 8];
      *(float4*)&a[4] = *(const float4*)&Xs[kk][tm * 8 + 4];
      ulonglong2 b01 = *(const ulonglong2*)&Ws[kk][tn * 8];
      ulonglong2 b23 = *(const ulonglong2*)&Ws[kk][tn * 8 + 4];
#pragma unroll
      for (int i = 0; i < 8; i++) {
        ull aa = packf2(a[i], a[i]);
        fma2(acc2[i][0], aa, b01.x);
        fma2(acc2[i][1], aa, b01.y);
        fma2(acc2[i][2], aa, b23.x);
        fma2(acc2[i][3], aa, b23.y);
      }
    }
  }

#pragma unroll
  for (int i = 0; i < 8; i++) {
    size_t row = (size_t)(m0 + tm * 8 + i);
    F2U u0, u1, u2, u3;
    u0.u = acc2[i][0]; u1.u = acc2[i][1];
    u2.u = acc2[i][2]; u3.u = acc2[i][3];
    float4 o0 = make_float4(u0.f.x, u0.f.y, u1.f.x, u1.f.y);
    float4 o1 = make_float4(u2.f.x, u2.f.y, u3.f.x, u3.f.y);
    *(float4*)&outp[row * DD + tn * 8] = o0;
    *(float4*)&outp[row * DD + tn * 8 + 4] = o1;
  }
}

// ---------------------------------------------------------------------------
// Causal flash attention v2: register softmax, warp-owned rows, packed PV.
// BQ=64, BK=32, D=128.  8 warps; warp w owns rows w*8..w*8+7.
// Thread (g=lane>>3, l8=lane&7): S rows {w*8+2g, +1} x cols {l8+8j}.
// Row stats via shfl.bfly in 8-lane groups; P via warp-private smem strip.
// PV: each lane accumulates all 8 warp rows x dv=lane*4..+3 (packed f32x2).
// CTA pairing over qblk for causal load balance (grid 16 x 8).
// ---------------------------------------------------------------------------
#define BQ 64
#define BK 32
#define SQ 132
#define SKS 132
#define SV 128
#define SP 36     // P stride per row

#define OFF_Q 0
#define OFF_K (OFF_Q + BQ * SQ)          // 8448
#define OFF_V (OFF_K + BK * SKS)         // 12672
#define OFF_P (OFF_V + BK * SV)          // 16768  (8 warps * 8 rows * 36)
#define OFF_AR (OFF_P + 8 * 8 * SP)      // 19072
#define OFF_LR (OFF_AR + BQ)
#define SMEM_FLOATS (OFF_LR + BQ)        // 19200 floats = 76800 B

__global__ __launch_bounds__(256) void attn_kernel(float* __restrict__ out) {
  extern __shared__ float sm_[];
  float* Qs = sm_ + OFF_Q;
  float* Ks = sm_ + OFF_K;
  float* Vs = sm_ + OFF_V;
  float* Ps = sm_ + OFF_P;
  float* arowS = sm_ + OFF_AR;
  float* lrowS = sm_ + OFF_LR;

  const int b = blockIdx.y;
  const int tid = threadIdx.x;
  const int w = tid >> 5;
  const int lane = tid & 31;
  const int g = lane >> 3;
  const int l8 = lane & 7;
  const float* __restrict__ qp = g_q + (size_t)b * TT * DD;
  const float* __restrict__ kp = g_k + (size_t)b * TT * DD;
  const float* __restrict__ vp = g_v + (size_t)b * TT * DD;
  const float scale = 0.08838834764831845f;  // 1/sqrt(128)

  const int r0 = w * 8 + g * 2;      // local row of this thread's stats
  float* Pw = Ps + w * 8 * SP;       // warp-private P strip [8][SP]

  for (int pass = 0; pass < 2; pass++) {
    const int qblk = pass ? (TT / BQ - 1 - (int)blockIdx.x) : (int)blockIdx.x;
    __syncthreads();  // previous pass done with Qs

    // Load Q tile (pre-scaled): 64x128
#pragma unroll
    for (int it = 0; it < 8; it++) {
      int idx = tid + it * 256;
      int r = idx >> 5;
      int d4 = (idx & 31) << 2;
      float4 v = *(const float4*)&qp[(size_t)(qblk * BQ + r) * DD + d4];
      v.x *= scale; v.y *= scale; v.z *= scale; v.w *= scale;
      *(float4*)&Qs[r * SQ + d4] = v;
    }

    float m2[2] = {-1e30f, -1e30f};
    float l2[2] = {0.f, 0.f};
    ull o2[8][2];
#pragma unroll
    for (int r = 0; r < 8; r++) { o2[r][0] = 0ull; o2[r][1] = 0ull; }

    const int nkt = 2 * (qblk + 1);
    for (int kt = 0; kt < nkt; kt++) {
      // Load K,V tiles: 32x128 each (float4 stores, conflict-free)
#pragma unroll
      for (int it = 0; it < 4; it++) {
        int idx = tid + it * 256;
        int r = idx >> 5;
        int d4 = (idx & 31) << 2;
        float4 kv = *(const float4*)&kp[(size_t)(kt * BK + r) * DD + d4];
        *(float4*)&Ks[r * SKS + d4] = kv;
        float4 vv = *(const float4*)&vp[(size_t)(kt * BK + r) * DD + d4];
        *(float4*)&Vs[r * SV + d4] = vv;
      }
      __syncthreads();

      // ---- S = Q K^T : 2 rows x 4 cols per thread, in registers ----
      float s[2][4];
#pragma unroll
      for (int i = 0; i < 2; i++)
#pragma unroll
        for (int j = 0; j < 4; j++) s[i][j] = 0.f;

#pragma unroll 8
      for (int d = 0; d < DD; d += 4) {
        float4 q0 = *(const float4*)&Qs[r0 * SQ + d];
        float4 q1 = *(const float4*)&Qs[(r0 + 1) * SQ + d];
        float4 k0 = *(const float4*)&Ks[l8 * SKS + d];
        float4 k1 = *(const float4*)&Ks[(l8 + 8) * SKS + d];
        float4 k2 = *(const float4*)&Ks[(l8 + 16) * SKS + d];
        float4 k3 = *(const float4*)&Ks[(l8 + 24) * SKS + d];
        s[0][0] += q0.x * k0.x + q0.y * k0.y + q0.z * k0.z + q0.w * k0.w;
        s[0][1] += q0.x * k1.x + q0.y * k1.y + q0.z * k1.z + q0.w * k1.w;
        s[0][2] += q0.x * k2.x + q0.y * k2.y + q0.z * k2.z + q0.w * k2.w;
        s[0][3] += q0.x * k3.x + q0.y * k3.y + q0.z * k3.z + q0.w * k3.w;
        s[1][0] += q1.x * k0.x + q1.y * k0.y + q1.z * k0.z + q1.w * k0.w;
        s[1][1] += q1.x * k1.x + q1.y * k1.y + q1.z * k1.z + q1.w * k1.w;
        s[1][2] += q1.x * k2.x + q1.y * k2.y + q1.z * k2.z + q1.w * k2.w;
        s[1][3] += q1.x * k3.x + q1.y * k3.y + q1.z * k3.z + q1.w * k3.w;
      }

      // Causal mask (diagonal tiles only)
      if (kt >= 2 * qblk) {
#pragma unroll
        for (int i = 0; i < 2; i++) {
          int qg = qblk * BQ + r0 + i;
#pragma unroll
          for (int j = 0; j < 4; j++) {
            int kg = kt * BK + l8 + 8 * j;
            if (kg > qg) s[i][j] = -1e30f;
          }
        }
      }

      // ---- online softmax, register-resident ----
      float al_i[2];
#pragma unroll
      for (int i = 0; i < 2; i++) {
        float vmax = fmaxf(fmaxf(s[i][0], s[i][1]), fmaxf(s[i][2], s[i][3]));
#pragma unroll
        for (int off = 1; off < 8; off <<= 1)
          vmax = fmaxf(vmax, __shfl_xor_sync(0xffffffffu, vmax, off));
        float mn = fmaxf(m2[i], vmax);
        al_i[i] = __expf(m2[i] - mn);
        float p0 = __expf(s[i][0] - mn);
        float p1 = __expf(s[i][1] - mn);
        float p2 = __expf(s[i][2] - mn);
        float p3 = __expf(s[i][3] - mn);
        float ps = p0 + p1 + p2 + p3;
#pragma unroll
        for (int off = 1; off < 8; off <<= 1)
          ps += __shfl_xor_sync(0xffffffffu, ps, off);
        l2[i] = l2[i] * al_i[i] + ps;
        m2[i] = mn;
        // write P row (conflict-free: banks 8g + l8 + 8j + 4i distinct)
        Pw[(g * 2 + i) * SP + l8] = p0;
        Pw[(g * 2 + i) * SP + l8 + 8] = p1;
        Pw[(g * 2 + i) * SP + l8 + 16] = p2;
        Pw[(g * 2 + i) * SP + l8 + 24] = p3;
      }
      if (l8 == 0) {
        arowS[r0] = al_i[0];
        arowS[r0 + 1] = al_i[1];
      }
      __syncwarp();

      // ---- rescale O by row alphas (all 8 warp rows) ----
#pragma unroll
      for (int r = 0; r < 8; r++) {
        float a = arowS[w * 8 + r];
        ull aa = packf2(a, a);
        o2[r][0] = mul2(o2[r][0], aa);
        o2[r][1] = mul2(o2[r][1], aa);
      }

      // ---- O += P @ V (packed f32x2 over dv) ----
#pragma unroll 2
      for (int k4 = 0; k4 < 8; k4++) {
        ulonglong2 vv[4];
#pragma unroll
        for (int kk = 0; kk < 4; kk++)
          vv[kk] = *(const ulonglong2*)&Vs[(k4 * 4 + kk) * SV + lane * 4];
#pragma unroll
        for (int r = 0; r < 8; r++) {
          float4 p4 = *(const float4*)&Pw[r * SP + k4 * 4];
          ull pp;
          pp = packf2(p4.x, p4.x);
          fma2(o2[r][0], pp, vv[0].x); fma2(o2[r][1], pp, vv[0].y);
          pp = packf2(p4.y, p4.y);
          fma2(o2[r][0], pp, vv[1].x); fma2(o2[r][1], pp, vv[1].y);
          pp = packf2(p4.z, p4.z);
          fma2(o2[r][0], pp, vv[2].x); fma2(o2[r][1], pp, vv[2].y);
          pp = packf2(p4.w, p4.w);
          fma2(o2[r][0], pp, vv[3].x); fma2(o2[r][1], pp, vv[3].y);
        }
      }
      __syncthreads();  // K/V/P consumed; safe to overwrite next tile
    }

    // ---- epilogue: divide by row sums, store ----
    if (l8 == 0) {
      lrowS[r0] = l2[0];
      lrowS[r0 + 1] = l2[1];
    }
    __syncwarp();
#pragma unroll
    for (int r = 0; r < 8; r++) {
      float inv = 1.f / lrowS[w * 8 + r];
      F2U u0, u1;
      u0.u = o2[r][0]; u1.u = o2[r][1];
      size_t base = ((size_t)b * TT + (size_t)qblk * BQ + w * 8 + r) * DD;
      float4 ov = make_float4(u0.f.x * inv, u0.f.y * inv,
                              u1.f.x * inv, u1.f.y * inv);
      *(float4*)&out[base + lane * 4] = ov;
    }
  }
}

// ---------------------------------------------------------------------------
extern "C" void kernel_launch(void* const* d_in, const int* in_sizes, int n_in,
                              void* d_out, int out_size) {
  const float* X = (const float*)d_in[0];
  const float* Wq = (const float*)d_in[1];
  const float* Wk = (const float*)d_in[2];
  const float* Wv = (const float*)d_in[3];
  float* out = (float*)d_out;

  qkv_gemm_kernel<<<dim3(128, 3), 256>>>(X, Wq, Wk, Wv);

  const int smem_bytes = SMEM_FLOATS * (int)sizeof(float);
  cudaFuncSetAttribute((const void*)attn_kernel,
                       cudaFuncAttributeMaxDynamicSharedMemorySize, smem_bytes);
  attn_kernel<<<dim3(16, BATCHN), 256, smem_bytes>>>(out);
}